// round 7
// baseline (speedup 1.0000x reference)
#include <cuda_runtime.h>
#include <cuda_bf16.h>
#include <cstdint>

#define VOCAB  50257
#define VPAD   50432          // 394 * 128
#define DMODEL 768
#define MTOT   4096           // B*S
#define SEQ    2048

#define BM 128
#define BN 128
#define BK 128                // int8: 128 B/row, SW128-native
#define STAGES 3
#define NKC (DMODEL / BK)     // 6
#define TILE_BYTES (BM * BK)             // 16384 (int8)
#define STAGE_BYTES (2 * TILE_BYTES)     // 32768
#define SMEM_BYTES (STAGES * STAGE_BYTES) // 98304 -> 2 CTAs/SM

// Scratch (static device globals — allocation-guard safe)
__device__ signed char g_w8[(size_t)VPAD * DMODEL];   // W^T int8 [v][k], pad rows zeroed
__device__ signed char g_a8[(size_t)(MTOT + SEQ) * DMODEL]; // rows 0..4095 tok, 4096..6143 pos
__device__ int         g_P[(size_t)SEQ * VPAD];       // P = wpe*W + bias, int32

// ---------------- helpers ----------------
__device__ __forceinline__ uint32_t smem_u32(const void* p) {
    return (uint32_t)__cvta_generic_to_shared(p);
}

__device__ __forceinline__ void ldsm4(uint32_t* r, uint32_t addr) {
    asm volatile("ldmatrix.sync.aligned.m8n8.x4.shared.b16 {%0,%1,%2,%3}, [%4];"
                 : "=r"(r[0]), "=r"(r[1]), "=r"(r[2]), "=r"(r[3]) : "r"(addr));
}

__device__ __forceinline__ void imma16832(int* c, const uint32_t* a, uint32_t b0, uint32_t b1) {
    asm volatile(
        "mma.sync.aligned.m16n8k32.row.col.s32.s8.s8.s32 "
        "{%0,%1,%2,%3}, {%4,%5,%6,%7}, {%8,%9}, {%0,%1,%2,%3};"
        : "+r"(c[0]), "+r"(c[1]), "+r"(c[2]), "+r"(c[3])
        : "r"(a[0]), "r"(a[1]), "r"(a[2]), "r"(a[3]), "r"(b0), "r"(b1));
}

__device__ __forceinline__ void cp16(uint32_t dst, const void* src) {
    asm volatile("cp.async.cg.shared.global [%0], [%1], 16;" :: "r"(dst), "l"(src));
}

// ---------------- prep 1: int8 A rows (token gather + position) ----------------
// wte/wpe arrive as int32 (harness-widened int8), values in [-127,127].
__global__ void packa_kernel(const int* __restrict__ ids,
                             const int* __restrict__ wte,
                             const int* __restrict__ wpe) {
    int m  = blockIdx.x;              // 0..6143
    int k4 = threadIdx.x * 4;         // 192 threads * 4 = 768
    const int* src;
    if (m < MTOT) src = wte + (size_t)ids[m] * DMODEL + k4;
    else          src = wpe + (size_t)(m - MTOT) * DMODEL + k4;
    int4 a = *(const int4*)src;
    char4 c = make_char4((char)a.x, (char)a.y, (char)a.z, (char)a.w);
    *(char4*)(g_a8 + (size_t)m * DMODEL + k4) = c;
}

// ---------------- prep 2: W^T int8 [VPAD,768] from int32 [768,VOCAB] ----------------
__global__ void packw_kernel(const int* __restrict__ w) {
    __shared__ signed char tile[32][33];
    int v0 = blockIdx.x * 32;   // vocab
    int k0 = blockIdx.y * 32;   // dmodel
    int tx = threadIdx.x, ty = threadIdx.y;  // (32, 8)
    #pragma unroll
    for (int j = 0; j < 32; j += 8) {
        int v = v0 + tx;
        int val = (v < VOCAB) ? w[(size_t)(k0 + ty + j) * VOCAB + v] : 0;
        tile[ty + j][tx] = (signed char)val;
    }
    __syncthreads();
    #pragma unroll
    for (int j = 0; j < 32; j += 8) {
        int v = v0 + ty + j;  // < VPAD
        g_w8[(size_t)v * DMODEL + (k0 + tx)] = tile[tx][ty + j];
    }
}

// ---------------- int8 GEMM core: 128x128 CTA, 32x64 warp, mma.s8 ----------------
// IS_P: A = pos rows, write P (int32, padded stride, +bias).
// else: A = tok rows, epilogue adds P, writes float out.
template <bool IS_P>
__global__ void __launch_bounds__(256, 2)
gemm_kernel(const int* __restrict__ bias, float* __restrict__ out) {
    extern __shared__ unsigned char smem[];
    const int tid  = threadIdx.x;
    const int wid  = tid >> 5;
    const int lane = tid & 31;
    const int m0 = blockIdx.x * BM;
    const int n0 = blockIdx.y * BN;
    const int wm = (wid & 3) * 32;   // warp m offset
    const int wn = (wid >> 2) * 64;  // warp n offset

    const uint32_t sbase = smem_u32(smem);
    const signed char* gA = g_a8 + (IS_P ? (size_t)(MTOT + m0) : (size_t)m0) * DMODEL;
    const signed char* gB = g_w8 + (size_t)n0 * DMODEL;

    // Per-thread cp.async coords: 128 rows x 8 chunks = 1024 -> 4 per thread (each tile)
    int lco[4];
    const signed char* lsa[4];
    const signed char* lsb[4];
    #pragma unroll
    for (int i = 0; i < 4; i++) {
        int idx = tid + i * 256;
        int r = idx >> 3, c = idx & 7;
        lco[i] = r * 128 + ((c ^ (r & 7)) << 4);
        lsa[i] = gA + (size_t)r * DMODEL + c * 16;
        lsb[i] = gB + (size_t)r * DMODEL + c * 16;
    }

    int acc[2][8][4];
    #pragma unroll
    for (int i = 0; i < 2; i++)
        #pragma unroll
        for (int j = 0; j < 8; j++)
            #pragma unroll
            for (int q = 0; q < 4; q++) acc[i][j][q] = 0;

    // ---- prefetch STAGES-1 stages ----
    #pragma unroll
    for (int s = 0; s < STAGES - 1; s++) {
        uint32_t dstA = sbase + s * STAGE_BYTES;
        uint32_t dstB = dstA + TILE_BYTES;
        #pragma unroll
        for (int i = 0; i < 4; i++) {
            cp16(dstA + lco[i], lsa[i] + s * BK);
            cp16(dstB + lco[i], lsb[i] + s * BK);
        }
        asm volatile("cp.async.commit_group;");
    }

    const int lrow = lane & 15;
    const int lhi  = lane >> 4;

    for (int kc = 0; kc < NKC; kc++) {
        asm volatile("cp.async.wait_group %0;" :: "n"(STAGES - 2));
        __syncthreads();

        const int st = kc % STAGES;
        const uint32_t baseA = sbase + st * STAGE_BYTES;
        const uint32_t baseB = baseA + TILE_BYTES;

        #pragma unroll
        for (int kk = 0; kk < 4; kk++) {       // 4 x K=32 steps per BK=128
            const int c = kk * 2 + lhi;        // 16B-chunk col
            uint32_t a[2][4], b[4][4];
            #pragma unroll
            for (int f = 0; f < 2; f++) {
                int r = wm + f * 16 + lrow;
                ldsm4(a[f], baseA + r * 128 + ((c ^ (r & 7)) << 4));
            }
            #pragma unroll
            for (int g = 0; g < 4; g++) {
                int r = wn + g * 16 + lrow;
                ldsm4(b[g], baseB + r * 128 + ((c ^ (r & 7)) << 4));
            }
            #pragma unroll
            for (int f = 0; f < 2; f++)
                #pragma unroll
                for (int g = 0; g < 4; g++) {
                    imma16832(acc[f][2 * g + 0], a[f], b[g][0], b[g][2]);
                    imma16832(acc[f][2 * g + 1], a[f], b[g][1], b[g][3]);
                }
        }

        const int nk = kc + STAGES - 1;
        if (nk < NKC) {
            const int st2 = nk % STAGES;
            uint32_t dstA = sbase + st2 * STAGE_BYTES;
            uint32_t dstB = dstA + TILE_BYTES;
            #pragma unroll
            for (int i = 0; i < 4; i++) {
                cp16(dstA + lco[i], lsa[i] + nk * BK);
                cp16(dstB + lco[i], lsb[i] + nk * BK);
            }
        }
        asm volatile("cp.async.commit_group;");
    }

    // ---- epilogue ----
    if (IS_P) {
        // P[r][col] = acc + bias (int32), padded stride VPAD -> int2 stores are 8B-aligned
        #pragma unroll
        for (int f = 0; f < 2; f++) {
            const int r = m0 + wm + f * 16 + (lane >> 2);
            int* row0 = g_P + (size_t)r * VPAD;
            int* row1 = row0 + (size_t)8 * VPAD;
            #pragma unroll
            for (int j = 0; j < 8; j++) {
                const int col = n0 + wn + j * 8 + ((lane & 3) << 1);
                const int b0 = (col < VOCAB) ? bias[col] : 0;
                const int b1 = (col + 1 < VOCAB) ? bias[col + 1] : 0;
                *(int2*)(row0 + col) = make_int2(acc[f][j][0] + b0, acc[f][j][1] + b1);
                *(int2*)(row1 + col) = make_int2(acc[f][j][2] + b0, acc[f][j][3] + b1);
            }
        }
    } else {
        // out[r][col] = float(acc + P[r & 2047][col]); scalar 4B stores (VOCAB odd)
        #pragma unroll
        for (int f = 0; f < 2; f++) {
            const int r = m0 + wm + f * 16 + (lane >> 2);
            const int* prow0 = g_P + (size_t)(r & (SEQ - 1)) * VPAD;
            const int* prow1 = prow0 + (size_t)8 * VPAD;
            float* row0 = out + (size_t)r * VOCAB;
            float* row1 = row0 + (size_t)8 * VOCAB;
            #pragma unroll
            for (int j = 0; j < 8; j++) {
                const int col = n0 + wn + j * 8 + ((lane & 3) << 1);
                int2 p0 = *(const int2*)(prow0 + col);
                int2 p1 = *(const int2*)(prow1 + col);
                if (col < VOCAB) {
                    row0[col] = (float)(acc[f][j][0] + p0.x);
                    row1[col] = (float)(acc[f][j][2] + p1.x);
                }
                if (col + 1 < VOCAB) {
                    row0[col + 1] = (float)(acc[f][j][1] + p0.y);
                    row1[col + 1] = (float)(acc[f][j][3] + p1.y);
                }
            }
        }
    }
}

// ---------------- launch ----------------
extern "C" void kernel_launch(void* const* d_in, const int* in_sizes, int n_in,
                              void* d_out, int out_size) {
    const int* ids  = (const int*)d_in[0];   // [2,2048] int32
    const int* wte  = (const int*)d_in[1];   // [50257,768] int8 widened to int32
    const int* wpe  = (const int*)d_in[2];   // [2048,768] int8 widened to int32
    const int* w    = (const int*)d_in[3];   // [768,50257] int32
    const int* bias = (const int*)d_in[4];   // [50257] int32
    float* out = (float*)d_out;              // [2,2048,50257] float32

    cudaFuncSetAttribute(gemm_kernel<true>,  cudaFuncAttributeMaxDynamicSharedMemorySize, SMEM_BYTES);
    cudaFuncSetAttribute(gemm_kernel<false>, cudaFuncAttributeMaxDynamicSharedMemorySize, SMEM_BYTES);

    packa_kernel<<<MTOT + SEQ, DMODEL / 4>>>(ids, wte, wpe);
    packw_kernel<<<dim3(VPAD / 32, DMODEL / 32), dim3(32, 8)>>>(w);
    // P = wpe*W + bias  (position GEMM, shared across batch)
    gemm_kernel<true><<<dim3(SEQ / BM, VPAD / BN), 256, SMEM_BYTES>>>(bias, nullptr);
    // out = wte[ids]*W + P
    gemm_kernel<false><<<dim3(MTOT / BM, VPAD / BN), 256, SMEM_BYTES>>>(bias, out);
}

// round 8
// speedup vs baseline: 2.7836x; 2.7836x over previous
#include <cuda_runtime.h>
#include <cuda_bf16.h>
#include <cstdint>

#define VOCAB  50257
#define VPAD   50304          // 393 * 128
#define DMODEL 768
#define MTOT   4096           // B*S
#define SEQ    2048

#define BM 128
#define BN 128
#define BK 64
#define STAGES 3
#define NKC (DMODEL / BK)                 // 12
#define TILE_BYTES (BM * BK * 2)          // 16384
#define STAGE_BYTES (2 * TILE_BYTES)      // 32768 (A + B)
#define SMEM_BYTES (STAGES * STAGE_BYTES) // 98304 -> 2 CTAs/SM

// Scratch (static device globals — allocation-guard safe)
__device__ __nv_bfloat16 g_wt[(size_t)VPAD * DMODEL];   // W^T [v][k], rows >= VOCAB zeroed
__device__ __nv_bfloat16 g_hid[(size_t)MTOT * DMODEL];  // hidden [m][k]
__device__ float         g_fb[VPAD];                    // float(bias), pad zeroed

// ---------------- helpers ----------------
__device__ __forceinline__ uint32_t smem_u32(const void* p) {
    return (uint32_t)__cvta_generic_to_shared(p);
}

__device__ __forceinline__ void ldsm4(uint32_t* r, uint32_t addr) {
    asm volatile("ldmatrix.sync.aligned.m8n8.x4.shared.b16 {%0,%1,%2,%3}, [%4];"
                 : "=r"(r[0]), "=r"(r[1]), "=r"(r[2]), "=r"(r[3]) : "r"(addr));
}

__device__ __forceinline__ void mma16816(float* c, const uint32_t* a, uint32_t b0, uint32_t b1) {
    asm volatile(
        "mma.sync.aligned.m16n8k16.row.col.f32.bf16.bf16.f32 "
        "{%0,%1,%2,%3}, {%4,%5,%6,%7}, {%8,%9}, {%0,%1,%2,%3};"
        : "+f"(c[0]), "+f"(c[1]), "+f"(c[2]), "+f"(c[3])
        : "r"(a[0]), "r"(a[1]), "r"(a[2]), "r"(a[3]), "r"(b0), "r"(b1));
}

__device__ __forceinline__ void cp16(uint32_t dst, const void* src) {
    asm volatile("cp.async.cg.shared.global [%0], [%1], 16;" :: "r"(dst), "l"(src));
}

// ---------------- prep 1: hidden = bf16(wte[id] + wpe[pos]) ----------------
// wte/wpe arrive as int32 (harness widens int8 inputs), values in [-127,127].
__global__ void embed_kernel(const int* __restrict__ ids,
                             const int* __restrict__ wte,
                             const int* __restrict__ wpe) {
    int m  = blockIdx.x;              // 0..4095
    int k4 = threadIdx.x * 4;         // 192 threads * 4 = 768
    int id  = ids[m];
    int pos = m & (SEQ - 1);
    int4 a = *(const int4*)(wte + (size_t)id  * DMODEL + k4);
    int4 p = *(const int4*)(wpe + (size_t)pos * DMODEL + k4);
    __nv_bfloat16 h[4];
    h[0] = __float2bfloat16((float)(a.x + p.x));
    h[1] = __float2bfloat16((float)(a.y + p.y));
    h[2] = __float2bfloat16((float)(a.z + p.z));
    h[3] = __float2bfloat16((float)(a.w + p.w));
    *(uint2*)(g_hid + (size_t)m * DMODEL + k4) = *(uint2*)h;
}

// ---------------- prep 2: W^T bf16 [VPAD,768] from int32 [768,VOCAB] ----------------
__global__ void packw_kernel(const int* __restrict__ w) {
    __shared__ __nv_bfloat16 tile[32][33];
    int v0 = blockIdx.x * 32;   // vocab
    int k0 = blockIdx.y * 32;   // dmodel
    int tx = threadIdx.x, ty = threadIdx.y;  // (32, 8)
    #pragma unroll
    for (int j = 0; j < 32; j += 8) {
        int v = v0 + tx;
        int val = (v < VOCAB) ? w[(size_t)(k0 + ty + j) * VOCAB + v] : 0;
        tile[ty + j][tx] = __float2bfloat16((float)val);
    }
    __syncthreads();
    #pragma unroll
    for (int j = 0; j < 32; j += 8) {
        int v = v0 + ty + j;  // < VPAD
        g_wt[(size_t)v * DMODEL + (k0 + tx)] = tile[tx][ty + j];
    }
}

// ---------------- prep 3: float bias table ----------------
__global__ void biasf_kernel(const int* __restrict__ bias) {
    int i = blockIdx.x * 256 + threadIdx.x;
    if (i < VPAD) g_fb[i] = (i < VOCAB) ? (float)bias[i] : 0.f;
}

// ---------------- main GEMM: 128x128 per CTA, warp 32x64, mma.sync bf16 ----------------
__global__ void __launch_bounds__(256, 2)
gemm_kernel(float* __restrict__ out) {
    extern __shared__ unsigned char smem[];
    const int tid  = threadIdx.x;
    const int wid  = tid >> 5;
    const int lane = tid & 31;
    const int m0 = blockIdx.x * BM;
    const int n0 = blockIdx.y * BN;
    const int wm = (wid & 3) * 32;   // warp m offset within CTA tile
    const int wn = (wid >> 2) * 64;  // warp n offset within CTA tile

    const uint32_t sbase = smem_u32(smem);
    const __nv_bfloat16* gA = g_hid + (size_t)m0 * DMODEL;
    const __nv_bfloat16* gB = g_wt  + (size_t)n0 * DMODEL;

    // Per-thread load coords: 4 x 16B chunks each for A and B per stage
    int lco[4];
    const __nv_bfloat16* lsa[4];
    const __nv_bfloat16* lsb[4];
    #pragma unroll
    for (int i = 0; i < 4; i++) {
        int idx = tid + i * 256;
        int r = idx >> 3, c = idx & 7;
        lco[i] = r * 128 + ((c ^ (r & 7)) << 4);
        lsa[i] = gA + (size_t)r * DMODEL + c * 8;
        lsb[i] = gB + (size_t)r * DMODEL + c * 8;
    }

    float acc[2][8][4];
    #pragma unroll
    for (int i = 0; i < 2; i++)
        #pragma unroll
        for (int j = 0; j < 8; j++)
            #pragma unroll
            for (int q = 0; q < 4; q++) acc[i][j][q] = 0.f;

    // ---- prefetch STAGES-1 stages ----
    #pragma unroll
    for (int s = 0; s < STAGES - 1; s++) {
        uint32_t dstA = sbase + s * STAGE_BYTES;
        uint32_t dstB = dstA + TILE_BYTES;
        #pragma unroll
        for (int i = 0; i < 4; i++) {
            cp16(dstA + lco[i], lsa[i] + s * BK);
            cp16(dstB + lco[i], lsb[i] + s * BK);
        }
        asm volatile("cp.async.commit_group;");
    }

    const int lrow = lane & 15;
    const int lhi  = lane >> 4;

    #pragma unroll 3
    for (int kc = 0; kc < NKC; kc++) {
        asm volatile("cp.async.wait_group %0;" :: "n"(STAGES - 2));
        __syncthreads();

        const int st = kc % STAGES;
        const uint32_t baseA = sbase + st * STAGE_BYTES;
        const uint32_t baseB = baseA + TILE_BYTES;

        #pragma unroll
        for (int kk = 0; kk < 4; kk++) {
            const int c = kk * 2 + lhi;  // 16B-chunk col
            uint32_t a[2][4], b[4][4];
            #pragma unroll
            for (int f = 0; f < 2; f++) {
                int r = wm + f * 16 + lrow;
                ldsm4(a[f], baseA + r * 128 + ((c ^ (r & 7)) << 4));
            }
            #pragma unroll
            for (int g = 0; g < 4; g++) {
                int r = wn + g * 16 + lrow;
                ldsm4(b[g], baseB + r * 128 + ((c ^ (r & 7)) << 4));
            }
            #pragma unroll
            for (int i = 0; i < 2; i++)
                #pragma unroll
                for (int g = 0; g < 4; g++) {
                    mma16816(acc[i][2 * g + 0], a[i], b[g][0], b[g][2]);
                    mma16816(acc[i][2 * g + 1], a[i], b[g][1], b[g][3]);
                }
        }

        const int nk = kc + STAGES - 1;
        if (nk < NKC) {
            const int st2 = nk % STAGES;
            uint32_t dstA = sbase + st2 * STAGE_BYTES;
            uint32_t dstB = dstA + TILE_BYTES;
            #pragma unroll
            for (int i = 0; i < 4; i++) {
                cp16(dstA + lco[i], lsa[i] + nk * BK);
                cp16(dstB + lco[i], lsb[i] + nk * BK);
            }
        }
        asm volatile("cp.async.commit_group;");
    }

    // ---- epilogue: out = acc + float(bias) ----
    // fp32 acc of integer products: error ≲ few ulps @2^24 on ~2e5-scale logits
    // => rel_err ~1e-5 << 1e-3. Single FADD per element instead of round+add+cvt.
    // Scalar 4B stores: rows only 4B-aligned (VOCAB odd).
    float fb0[8], fb1[8];
    #pragma unroll
    for (int j = 0; j < 8; j++) {
        const int col = n0 + wn + j * 8 + ((lane & 3) << 1);
        fb0[j] = g_fb[col];        // col < VPAD always; pad entries are 0
        fb1[j] = g_fb[col + 1 < VPAD ? col + 1 : col];
    }
    #pragma unroll
    for (int i = 0; i < 2; i++) {
        const int r = m0 + wm + i * 16 + (lane >> 2);
        float* row0 = out + (size_t)r * VOCAB;
        float* row1 = row0 + (size_t)8 * VOCAB;
        #pragma unroll
        for (int j = 0; j < 8; j++) {
            const int col = n0 + wn + j * 8 + ((lane & 3) << 1);
            if (col < VOCAB) {
                row0[col] = acc[i][j][0] + fb0[j];
                row1[col] = acc[i][j][2] + fb0[j];
            }
            if (col + 1 < VOCAB) {
                row0[col + 1] = acc[i][j][1] + fb1[j];
                row1[col + 1] = acc[i][j][3] + fb1[j];
            }
        }
    }
}

// ---------------- launch ----------------
extern "C" void kernel_launch(void* const* d_in, const int* in_sizes, int n_in,
                              void* d_out, int out_size) {
    const int* ids  = (const int*)d_in[0];   // [2,2048] int32
    const int* wte  = (const int*)d_in[1];   // [50257,768] int8 widened to int32
    const int* wpe  = (const int*)d_in[2];   // [2048,768] int8 widened to int32
    const int* w    = (const int*)d_in[3];   // [768,50257] int32
    const int* bias = (const int*)d_in[4];   // [50257] int32
    float* out = (float*)d_out;              // [2,2048,50257] float32

    cudaFuncSetAttribute(gemm_kernel, cudaFuncAttributeMaxDynamicSharedMemorySize, SMEM_BYTES);

    embed_kernel<<<MTOT, DMODEL / 4>>>(ids, wte, wpe);
    biasf_kernel<<<(VPAD + 255) / 256, 256>>>(bias);
    packw_kernel<<<dim3(VPAD / 32, DMODEL / 32), dim3(32, 8)>>>(w);
    gemm_kernel<<<dim3(MTOT / BM, VPAD / BN), 256, SMEM_BYTES>>>(out);
}

// round 9
// speedup vs baseline: 2.8520x; 1.0246x over previous
#include <cuda_runtime.h>
#include <cuda_bf16.h>
#include <cstdint>

#define VOCAB  50257
#define VPAD   50304          // 393 * 128
#define DMODEL 768
#define MTOT   4096           // B*S
#define SEQ    2048

#define BM 128
#define BN 128
#define BK 64
#define STAGES 3
#define NKC (DMODEL / BK)                 // 12
#define TILE_BYTES (BM * BK * 2)          // 16384
#define STAGE_BYTES (2 * TILE_BYTES)      // 32768 (A + B)
#define SMEM_BYTES (STAGES * STAGE_BYTES) // 98304 -> 2 CTAs/SM

// Scratch (static device globals — allocation-guard safe)
__device__ __nv_bfloat16 g_wt[(size_t)VPAD * DMODEL];   // W^T [v][k], rows >= VOCAB zeroed
__device__ __nv_bfloat16 g_hid[(size_t)MTOT * DMODEL];  // hidden [m][k]
__device__ float         g_fb[VPAD];                    // float(bias), pad zeroed

// ---------------- helpers ----------------
__device__ __forceinline__ uint32_t smem_u32(const void* p) {
    return (uint32_t)__cvta_generic_to_shared(p);
}

__device__ __forceinline__ void ldsm4(uint32_t* r, uint32_t addr) {
    asm volatile("ldmatrix.sync.aligned.m8n8.x4.shared.b16 {%0,%1,%2,%3}, [%4];"
                 : "=r"(r[0]), "=r"(r[1]), "=r"(r[2]), "=r"(r[3]) : "r"(addr));
}

__device__ __forceinline__ void mma16816(float* c, const uint32_t* a, uint32_t b0, uint32_t b1) {
    asm volatile(
        "mma.sync.aligned.m16n8k16.row.col.f32.bf16.bf16.f32 "
        "{%0,%1,%2,%3}, {%4,%5,%6,%7}, {%8,%9}, {%0,%1,%2,%3};"
        : "+f"(c[0]), "+f"(c[1]), "+f"(c[2]), "+f"(c[3])
        : "r"(a[0]), "r"(a[1]), "r"(a[2]), "r"(a[3]), "r"(b0), "r"(b1));
}

__device__ __forceinline__ void cp16(uint32_t dst, const void* src) {
    asm volatile("cp.async.cg.shared.global [%0], [%1], 16;" :: "r"(dst), "l"(src));
}

// ---------------- prep 1: hidden = bf16(wte[id] + wpe[pos]) ----------------
__global__ void embed_kernel(const int* __restrict__ ids,
                             const int* __restrict__ wte,
                             const int* __restrict__ wpe) {
    int m  = blockIdx.x;              // 0..4095
    int k4 = threadIdx.x * 4;         // 192 threads * 4 = 768
    int id  = ids[m];
    int pos = m & (SEQ - 1);
    int4 a = *(const int4*)(wte + (size_t)id  * DMODEL + k4);
    int4 p = *(const int4*)(wpe + (size_t)pos * DMODEL + k4);
    __nv_bfloat16 h[4];
    h[0] = __float2bfloat16((float)(a.x + p.x));
    h[1] = __float2bfloat16((float)(a.y + p.y));
    h[2] = __float2bfloat16((float)(a.z + p.z));
    h[3] = __float2bfloat16((float)(a.w + p.w));
    *(uint2*)(g_hid + (size_t)m * DMODEL + k4) = *(uint2*)h;
}

// ---------------- prep 2: W^T bf16 [VPAD,768] from int32 [768,VOCAB] ----------------
__global__ void packw_kernel(const int* __restrict__ w) {
    __shared__ __nv_bfloat16 tile[32][33];
    int v0 = blockIdx.x * 32;   // vocab
    int k0 = blockIdx.y * 32;   // dmodel
    int tx = threadIdx.x, ty = threadIdx.y;  // (32, 8)
    #pragma unroll
    for (int j = 0; j < 32; j += 8) {
        int v = v0 + tx;
        int val = (v < VOCAB) ? w[(size_t)(k0 + ty + j) * VOCAB + v] : 0;
        tile[ty + j][tx] = __float2bfloat16((float)val);
    }
    __syncthreads();
    #pragma unroll
    for (int j = 0; j < 32; j += 8) {
        int v = v0 + ty + j;  // < VPAD
        g_wt[(size_t)v * DMODEL + (k0 + tx)] = tile[tx][ty + j];
    }
}

// ---------------- prep 3: float bias table ----------------
__global__ void biasf_kernel(const int* __restrict__ bias) {
    int i = blockIdx.x * 256 + threadIdx.x;
    if (i < VPAD) g_fb[i] = (i < VOCAB) ? (float)bias[i] : 0.f;
}

// ---------------- main GEMM: 128x128 CTA, 4 warps of 64x64, mma.sync bf16 ----------------
__global__ void __launch_bounds__(128, 2)
gemm_kernel(float* __restrict__ out) {
    extern __shared__ unsigned char smem[];
    const int tid  = threadIdx.x;
    const int wid  = tid >> 5;
    const int lane = tid & 31;
    const int m0 = blockIdx.x * BM;
    const int n0 = blockIdx.y * BN;
    const int wm = (wid & 1) * 64;   // 2 warps in m
    const int wn = (wid >> 1) * 64;  // 2 warps in n

    const uint32_t sbase = smem_u32(smem);
    const __nv_bfloat16* gA = g_hid + (size_t)m0 * DMODEL;
    const __nv_bfloat16* gB = g_wt  + (size_t)n0 * DMODEL;

    // Per-thread cp.async coords: 1024 chunks per tile / 128 threads = 8 each
    int lco[8];
    const __nv_bfloat16* lsa[8];
    const __nv_bfloat16* lsb[8];
    #pragma unroll
    for (int i = 0; i < 8; i++) {
        int idx = tid + i * 128;
        int r = idx >> 3, c = idx & 7;
        lco[i] = r * 128 + ((c ^ (r & 7)) << 4);
        lsa[i] = gA + (size_t)r * DMODEL + c * 8;
        lsb[i] = gB + (size_t)r * DMODEL + c * 8;
    }

    float acc[4][8][4];
    #pragma unroll
    for (int f = 0; f < 4; f++)
        #pragma unroll
        for (int j = 0; j < 8; j++)
            #pragma unroll
            for (int q = 0; q < 4; q++) acc[f][j][q] = 0.f;

    // ---- prefetch STAGES-1 stages ----
    #pragma unroll
    for (int s = 0; s < STAGES - 1; s++) {
        uint32_t dstA = sbase + s * STAGE_BYTES;
        uint32_t dstB = dstA + TILE_BYTES;
        #pragma unroll
        for (int i = 0; i < 8; i++) {
            cp16(dstA + lco[i], lsa[i] + s * BK);
            cp16(dstB + lco[i], lsb[i] + s * BK);
        }
        asm volatile("cp.async.commit_group;");
    }

    const int lrow = lane & 15;
    const int lhi  = lane >> 4;

    #pragma unroll 3
    for (int kc = 0; kc < NKC; kc++) {
        asm volatile("cp.async.wait_group %0;" :: "n"(STAGES - 2));
        __syncthreads();

        const int st = kc % STAGES;
        const uint32_t baseA = sbase + st * STAGE_BYTES;
        const uint32_t baseB = baseA + TILE_BYTES;

        // fragment double-buffer: load kk+1 while mma kk
        uint32_t afr[2][4][4], bfr[2][4][4];
        {
            const int c0 = lhi;  // kk=0
            #pragma unroll
            for (int f = 0; f < 4; f++) {
                int r = wm + f * 16 + lrow;
                ldsm4(afr[0][f], baseA + r * 128 + ((c0 ^ (r & 7)) << 4));
            }
            #pragma unroll
            for (int g = 0; g < 4; g++) {
                int r = wn + g * 16 + lrow;
                ldsm4(bfr[0][g], baseB + r * 128 + ((c0 ^ (r & 7)) << 4));
            }
        }

        #pragma unroll
        for (int kk = 0; kk < 4; kk++) {
            const int cur = kk & 1;
            const int nxt = cur ^ 1;
            if (kk < 3) {
                const int c = (kk + 1) * 2 + lhi;
                #pragma unroll
                for (int f = 0; f < 4; f++) {
                    int r = wm + f * 16 + lrow;
                    ldsm4(afr[nxt][f], baseA + r * 128 + ((c ^ (r & 7)) << 4));
                }
                #pragma unroll
                for (int g = 0; g < 4; g++) {
                    int r = wn + g * 16 + lrow;
                    ldsm4(bfr[nxt][g], baseB + r * 128 + ((c ^ (r & 7)) << 4));
                }
            }
            #pragma unroll
            for (int f = 0; f < 4; f++)
                #pragma unroll
                for (int g = 0; g < 4; g++) {
                    mma16816(acc[f][2 * g + 0], afr[cur][f], bfr[cur][g][0], bfr[cur][g][2]);
                    mma16816(acc[f][2 * g + 1], afr[cur][f], bfr[cur][g][1], bfr[cur][g][3]);
                }
        }

        const int nk = kc + STAGES - 1;
        if (nk < NKC) {
            const int st2 = nk % STAGES;
            uint32_t dstA = sbase + st2 * STAGE_BYTES;
            uint32_t dstB = dstA + TILE_BYTES;
            #pragma unroll
            for (int i = 0; i < 8; i++) {
                cp16(dstA + lco[i], lsa[i] + nk * BK);
                cp16(dstB + lco[i], lsb[i] + nk * BK);
            }
        }
        asm volatile("cp.async.commit_group;");
    }

    // ---- epilogue: out = acc + float(bias); scalar 4B stores (VOCAB odd) ----
    float fb0[8], fb1[8];
    #pragma unroll
    for (int j = 0; j < 8; j++) {
        const int col = n0 + wn + j * 8 + ((lane & 3) << 1);
        fb0[j] = g_fb[col];
        fb1[j] = g_fb[col + 1 < VPAD ? col + 1 : col];
    }
    #pragma unroll
    for (int f = 0; f < 4; f++) {
        const int r = m0 + wm + f * 16 + (lane >> 2);
        float* row0 = out + (size_t)r * VOCAB;
        float* row1 = row0 + (size_t)8 * VOCAB;
        #pragma unroll
        for (int j = 0; j < 8; j++) {
            const int col = n0 + wn + j * 8 + ((lane & 3) << 1);
            if (col < VOCAB) {
                row0[col] = acc[f][j][0] + fb0[j];
                row1[col] = acc[f][j][2] + fb0[j];
            }
            if (col + 1 < VOCAB) {
                row0[col + 1] = acc[f][j][1] + fb1[j];
                row1[col + 1] = acc[f][j][3] + fb1[j];
            }
        }
    }
}

// ---------------- launch ----------------
extern "C" void kernel_launch(void* const* d_in, const int* in_sizes, int n_in,
                              void* d_out, int out_size) {
    const int* ids  = (const int*)d_in[0];   // [2,2048] int32
    const int* wte  = (const int*)d_in[1];   // [50257,768] int8 widened to int32
    const int* wpe  = (const int*)d_in[2];   // [2048,768] int8 widened to int32
    const int* w    = (const int*)d_in[3];   // [768,50257] int32
    const int* bias = (const int*)d_in[4];   // [50257] int32
    float* out = (float*)d_out;              // [2,2048,50257] float32

    cudaFuncSetAttribute(gemm_kernel, cudaFuncAttributeMaxDynamicSharedMemorySize, SMEM_BYTES);

    embed_kernel<<<MTOT, DMODEL / 4>>>(ids, wte, wpe);
    biasf_kernel<<<(VPAD + 255) / 256, 256>>>(bias);
    packw_kernel<<<dim3(VPAD / 32, DMODEL / 32), dim3(32, 8)>>>(w);
    gemm_kernel<<<dim3(MTOT / BM, VPAD / BN), 128, SMEM_BYTES>>>(out);
}

// round 10
// speedup vs baseline: 2.9488x; 1.0340x over previous
#include <cuda_runtime.h>
#include <cuda_bf16.h>
#include <cstdint>

#define VOCAB  50257
#define VPAD   50304          // 786 * 64
#define DMODEL 768
#define MTOT   4096           // B*S
#define SEQ    2048

#define BM 128
#define BN 64
#define BK 64
#define STAGES 3
#define NKC (DMODEL / BK)                  // 12
#define A_TILE_BYTES (BM * BK * 2)         // 16384
#define B_TILE_BYTES (BN * BK * 2)         // 8192
#define STAGE_BYTES (A_TILE_BYTES + B_TILE_BYTES)  // 24576
#define SMEM_BYTES (STAGES * STAGE_BYTES)  // 73728 -> 3 CTAs/SM

// Scratch (static device globals — allocation-guard safe)
__device__ __nv_bfloat16 g_wt[(size_t)VPAD * DMODEL];   // W^T [v][k], rows >= VOCAB zeroed
__device__ __nv_bfloat16 g_hid[(size_t)MTOT * DMODEL];  // hidden [m][k]
__device__ float         g_fb[VPAD];                    // float(bias), pad zeroed

// ---------------- helpers ----------------
__device__ __forceinline__ uint32_t smem_u32(const void* p) {
    return (uint32_t)__cvta_generic_to_shared(p);
}

__device__ __forceinline__ void ldsm4(uint32_t* r, uint32_t addr) {
    asm volatile("ldmatrix.sync.aligned.m8n8.x4.shared.b16 {%0,%1,%2,%3}, [%4];"
                 : "=r"(r[0]), "=r"(r[1]), "=r"(r[2]), "=r"(r[3]) : "r"(addr));
}

__device__ __forceinline__ void mma16816(float* c, const uint32_t* a, uint32_t b0, uint32_t b1) {
    asm volatile(
        "mma.sync.aligned.m16n8k16.row.col.f32.bf16.bf16.f32 "
        "{%0,%1,%2,%3}, {%4,%5,%6,%7}, {%8,%9}, {%0,%1,%2,%3};"
        : "+f"(c[0]), "+f"(c[1]), "+f"(c[2]), "+f"(c[3])
        : "r"(a[0]), "r"(a[1]), "r"(a[2]), "r"(a[3]), "r"(b0), "r"(b1));
}

__device__ __forceinline__ void cp16(uint32_t dst, const void* src) {
    asm volatile("cp.async.cg.shared.global [%0], [%1], 16;" :: "r"(dst), "l"(src));
}

// ---------------- prep 1: hidden = bf16(wte[id] + wpe[pos]) ----------------
__global__ void embed_kernel(const int* __restrict__ ids,
                             const int* __restrict__ wte,
                             const int* __restrict__ wpe) {
    int m  = blockIdx.x;              // 0..4095
    int k4 = threadIdx.x * 4;         // 192 threads * 4 = 768
    int id  = ids[m];
    int pos = m & (SEQ - 1);
    int4 a = *(const int4*)(wte + (size_t)id  * DMODEL + k4);
    int4 p = *(const int4*)(wpe + (size_t)pos * DMODEL + k4);
    __nv_bfloat16 h[4];
    h[0] = __float2bfloat16((float)(a.x + p.x));
    h[1] = __float2bfloat16((float)(a.y + p.y));
    h[2] = __float2bfloat16((float)(a.z + p.z));
    h[3] = __float2bfloat16((float)(a.w + p.w));
    *(uint2*)(g_hid + (size_t)m * DMODEL + k4) = *(uint2*)h;
}

// ---------------- prep 2: W^T bf16 [VPAD,768] from int32 [768,VOCAB] ----------------
__global__ void packw_kernel(const int* __restrict__ w) {
    __shared__ __nv_bfloat16 tile[32][33];
    int v0 = blockIdx.x * 32;   // vocab
    int k0 = blockIdx.y * 32;   // dmodel
    int tx = threadIdx.x, ty = threadIdx.y;  // (32, 8)
    #pragma unroll
    for (int j = 0; j < 32; j += 8) {
        int v = v0 + tx;
        int val = (v < VOCAB) ? w[(size_t)(k0 + ty + j) * VOCAB + v] : 0;
        tile[ty + j][tx] = __float2bfloat16((float)val);
    }
    __syncthreads();
    #pragma unroll
    for (int j = 0; j < 32; j += 8) {
        int v = v0 + ty + j;  // < VPAD
        g_wt[(size_t)v * DMODEL + (k0 + tx)] = tile[tx][ty + j];
    }
}

// ---------------- prep 3: float bias table ----------------
__global__ void biasf_kernel(const int* __restrict__ bias) {
    int i = blockIdx.x * 256 + threadIdx.x;
    if (i < VPAD) g_fb[i] = (i < VOCAB) ? (float)bias[i] : 0.f;
}

// ---------------- main GEMM: 128x64 CTA, 4 warps of 64x32, 3 CTAs/SM ----------------
__global__ void __launch_bounds__(128, 3)
gemm_kernel(float* __restrict__ out) {
    extern __shared__ unsigned char smem[];
    const int tid  = threadIdx.x;
    const int wid  = tid >> 5;
    const int lane = tid & 31;
    const int m0 = blockIdx.x * BM;
    const int n0 = blockIdx.y * BN;
    const int wm = (wid & 1) * 64;   // 2 warps in m
    const int wn = (wid >> 1) * 32;  // 2 warps in n

    const uint32_t sbase = smem_u32(smem);
    const __nv_bfloat16* gA = g_hid + (size_t)m0 * DMODEL;
    const __nv_bfloat16* gB = g_wt  + (size_t)n0 * DMODEL;

    // Per-thread cp.async coords: A 1024 chunks -> 8/thread; B 512 chunks -> 4/thread
    int lcoA[8], lcoB[4];
    const __nv_bfloat16* lsa[8];
    const __nv_bfloat16* lsb[4];
    #pragma unroll
    for (int i = 0; i < 8; i++) {
        int idx = tid + i * 128;
        int r = idx >> 3, c = idx & 7;
        lcoA[i] = r * 128 + ((c ^ (r & 7)) << 4);
        lsa[i]  = gA + (size_t)r * DMODEL + c * 8;
    }
    #pragma unroll
    for (int i = 0; i < 4; i++) {
        int idx = tid + i * 128;
        int r = idx >> 3, c = idx & 7;
        lcoB[i] = r * 128 + ((c ^ (r & 7)) << 4);
        lsb[i]  = gB + (size_t)r * DMODEL + c * 8;
    }

    float acc[4][4][4];
    #pragma unroll
    for (int f = 0; f < 4; f++)
        #pragma unroll
        for (int j = 0; j < 4; j++)
            #pragma unroll
            for (int q = 0; q < 4; q++) acc[f][j][q] = 0.f;

    // ---- prefetch STAGES-1 stages ----
    #pragma unroll
    for (int s = 0; s < STAGES - 1; s++) {
        uint32_t dstA = sbase + s * STAGE_BYTES;
        uint32_t dstB = dstA + A_TILE_BYTES;
        #pragma unroll
        for (int i = 0; i < 8; i++) cp16(dstA + lcoA[i], lsa[i] + s * BK);
        #pragma unroll
        for (int i = 0; i < 4; i++) cp16(dstB + lcoB[i], lsb[i] + s * BK);
        asm volatile("cp.async.commit_group;");
    }

    const int lrow = lane & 15;
    const int lhi  = lane >> 4;

    #pragma unroll 3
    for (int kc = 0; kc < NKC; kc++) {
        asm volatile("cp.async.wait_group %0;" :: "n"(STAGES - 2));
        __syncthreads();

        const int st = kc % STAGES;
        const uint32_t baseA = sbase + st * STAGE_BYTES;
        const uint32_t baseB = baseA + A_TILE_BYTES;

        // issue next-stage loads first (deeper latency hiding)
        const int nk = kc + STAGES - 1;
        if (nk < NKC) {
            const int st2 = nk % STAGES;
            uint32_t dstA = sbase + st2 * STAGE_BYTES;
            uint32_t dstB = dstA + A_TILE_BYTES;
            #pragma unroll
            for (int i = 0; i < 8; i++) cp16(dstA + lcoA[i], lsa[i] + nk * BK);
            #pragma unroll
            for (int i = 0; i < 4; i++) cp16(dstB + lcoB[i], lsb[i] + nk * BK);
        }
        asm volatile("cp.async.commit_group;");

        #pragma unroll
        for (int kk = 0; kk < 4; kk++) {
            const int c = kk * 2 + lhi;  // 16B-chunk col
            uint32_t a[4][4], b[2][4];
            #pragma unroll
            for (int f = 0; f < 4; f++) {
                int r = wm + f * 16 + lrow;
                ldsm4(a[f], baseA + r * 128 + ((c ^ (r & 7)) << 4));
            }
            #pragma unroll
            for (int g = 0; g < 2; g++) {
                int r = wn + g * 16 + lrow;
                ldsm4(b[g], baseB + r * 128 + ((c ^ (r & 7)) << 4));
            }
            #pragma unroll
            for (int f = 0; f < 4; f++)
                #pragma unroll
                for (int g = 0; g < 2; g++) {
                    mma16816(acc[f][2 * g + 0], a[f], b[g][0], b[g][2]);
                    mma16816(acc[f][2 * g + 1], a[f], b[g][1], b[g][3]);
                }
        }
    }

    // ---- epilogue: out = acc + float(bias); scalar 4B stores (VOCAB odd) ----
    float fb0[4], fb1[4];
    #pragma unroll
    for (int j = 0; j < 4; j++) {
        const int col = n0 + wn + j * 8 + ((lane & 3) << 1);
        fb0[j] = g_fb[col];
        fb1[j] = g_fb[col + 1 < VPAD ? col + 1 : col];
    }
    #pragma unroll
    for (int f = 0; f < 4; f++) {
        const int r = m0 + wm + f * 16 + (lane >> 2);
        float* row0 = out + (size_t)r * VOCAB;
        float* row1 = row0 + (size_t)8 * VOCAB;
        #pragma unroll
        for (int j = 0; j < 4; j++) {
            const int col = n0 + wn + j * 8 + ((lane & 3) << 1);
            if (col < VOCAB) {
                row0[col] = acc[f][j][0] + fb0[j];
                row1[col] = acc[f][j][2] + fb0[j];
            }
            if (col + 1 < VOCAB) {
                row0[col + 1] = acc[f][j][1] + fb1[j];
                row1[col + 1] = acc[f][j][3] + fb1[j];
            }
        }
    }
}

// ---------------- launch ----------------
extern "C" void kernel_launch(void* const* d_in, const int* in_sizes, int n_in,
                              void* d_out, int out_size) {
    const int* ids  = (const int*)d_in[0];   // [2,2048] int32
    const int* wte  = (const int*)d_in[1];   // [50257,768] int8 widened to int32
    const int* wpe  = (const int*)d_in[2];   // [2048,768] int8 widened to int32
    const int* w    = (const int*)d_in[3];   // [768,50257] int32
    const int* bias = (const int*)d_in[4];   // [50257] int32
    float* out = (float*)d_out;              // [2,2048,50257] float32

    cudaFuncSetAttribute(gemm_kernel, cudaFuncAttributeMaxDynamicSharedMemorySize, SMEM_BYTES);

    embed_kernel<<<MTOT, DMODEL / 4>>>(ids, wte, wpe);
    biasf_kernel<<<(VPAD + 255) / 256, 256>>>(bias);
    packw_kernel<<<dim3((VPAD + 31) / 32, DMODEL / 32), dim3(32, 8)>>>(w);
    gemm_kernel<<<dim3(MTOT / BM, VPAD / BN), 128, SMEM_BYTES>>>(out);
}

// round 11
// speedup vs baseline: 2.9592x; 1.0035x over previous
#include <cuda_runtime.h>
#include <cuda_bf16.h>
#include <cstdint>

#define VOCAB  50257
#define VPAD   50304          // 786 * 64, also 1572 * 32
#define DMODEL 768
#define MTOT   4096           // B*S
#define SEQ    2048

#define BM 128
#define BN 64
#define BK 64
#define STAGES 3
#define NKC (DMODEL / BK)                  // 12
#define A_TILE_BYTES (BM * BK * 2)         // 16384
#define B_TILE_BYTES (BN * BK * 2)         // 8192
#define STAGE_BYTES (A_TILE_BYTES + B_TILE_BYTES)  // 24576
#define SMEM_BYTES (STAGES * STAGE_BYTES)  // 73728 -> 3 CTAs/SM

// prep kernel block ranges
#define PW_BLOCKS ((VPAD / 32) * (DMODEL / 32))   // 1572*24 = 37728
#define EM_BLOCKS MTOT                            // 4096
#define BI_BLOCKS ((VPAD + 255) / 256)            // 197
#define PREP_GRID (PW_BLOCKS + EM_BLOCKS + BI_BLOCKS)

// Scratch (static device globals — allocation-guard safe)
__device__ __nv_bfloat16 g_wt[(size_t)VPAD * DMODEL];   // W^T [v][k], rows >= VOCAB zeroed
__device__ __nv_bfloat16 g_hid[(size_t)MTOT * DMODEL];  // hidden [m][k]
__device__ float         g_fb[VPAD];                    // float(bias), pad zeroed

// ---------------- helpers ----------------
__device__ __forceinline__ uint32_t smem_u32(const void* p) {
    return (uint32_t)__cvta_generic_to_shared(p);
}

__device__ __forceinline__ void ldsm4(uint32_t* r, uint32_t addr) {
    asm volatile("ldmatrix.sync.aligned.m8n8.x4.shared.b16 {%0,%1,%2,%3}, [%4];"
                 : "=r"(r[0]), "=r"(r[1]), "=r"(r[2]), "=r"(r[3]) : "r"(addr));
}

__device__ __forceinline__ void mma16816(float* c, const uint32_t* a, uint32_t b0, uint32_t b1) {
    asm volatile(
        "mma.sync.aligned.m16n8k16.row.col.f32.bf16.bf16.f32 "
        "{%0,%1,%2,%3}, {%4,%5,%6,%7}, {%8,%9}, {%0,%1,%2,%3};"
        : "+f"(c[0]), "+f"(c[1]), "+f"(c[2]), "+f"(c[3])
        : "r"(a[0]), "r"(a[1]), "r"(a[2]), "r"(a[3]), "r"(b0), "r"(b1));
}

__device__ __forceinline__ void cp16(uint32_t dst, const void* src) {
    asm volatile("cp.async.cg.shared.global [%0], [%1], 16;" :: "r"(dst), "l"(src));
}

// ---------------- fused prep: W^T transpose + embed gather + float bias ----------------
// wte/wpe arrive as int32 (harness widens int8 inputs), values in [-127,127].
__global__ void __launch_bounds__(256)
prep_kernel(const int* __restrict__ ids,
            const int* __restrict__ wte,
            const int* __restrict__ wpe,
            const int* __restrict__ w,
            const int* __restrict__ bias) {
    __shared__ __nv_bfloat16 tile[32][33];
    const int b = blockIdx.x;

    if (b < PW_BLOCKS) {
        // --- packw: W^T bf16 [VPAD,768] from int32 [768,VOCAB] ---
        int v0 = (b % (VPAD / 32)) * 32;
        int k0 = (b / (VPAD / 32)) * 32;
        int tx = threadIdx.x & 31, ty = threadIdx.x >> 5;  // (32, 8)
        #pragma unroll
        for (int j = 0; j < 32; j += 8) {
            int v = v0 + tx;
            int val = (v < VOCAB) ? w[(size_t)(k0 + ty + j) * VOCAB + v] : 0;
            tile[ty + j][tx] = __float2bfloat16((float)val);
        }
        __syncthreads();
        #pragma unroll
        for (int j = 0; j < 32; j += 8) {
            int v = v0 + ty + j;  // < VPAD
            g_wt[(size_t)v * DMODEL + (k0 + tx)] = tile[tx][ty + j];
        }
    } else if (b < PW_BLOCKS + EM_BLOCKS) {
        // --- embed: hidden = bf16(wte[id] + wpe[pos]) ---
        int m = b - PW_BLOCKS;            // 0..4095
        int t = threadIdx.x;
        if (t < 192) {
            int k4 = t * 4;
            int id  = ids[m];
            int pos = m & (SEQ - 1);
            int4 a = *(const int4*)(wte + (size_t)id  * DMODEL + k4);
            int4 p = *(const int4*)(wpe + (size_t)pos * DMODEL + k4);
            __nv_bfloat16 h[4];
            h[0] = __float2bfloat16((float)(a.x + p.x));
            h[1] = __float2bfloat16((float)(a.y + p.y));
            h[2] = __float2bfloat16((float)(a.z + p.z));
            h[3] = __float2bfloat16((float)(a.w + p.w));
            *(uint2*)(g_hid + (size_t)m * DMODEL + k4) = *(uint2*)h;
        }
    } else {
        // --- bias -> float table, pad zeroed ---
        int i = (b - PW_BLOCKS - EM_BLOCKS) * 256 + threadIdx.x;
        if (i < VPAD) g_fb[i] = (i < VOCAB) ? (float)bias[i] : 0.f;
    }
}

// ---------------- main GEMM: 128x64 CTA, 4 warps of 64x32, 3 CTAs/SM ----------------
// (unchanged from R10 — measured at the legacy mma.sync issue floor)
__global__ void __launch_bounds__(128, 3)
gemm_kernel(float* __restrict__ out) {
    extern __shared__ unsigned char smem[];
    const int tid  = threadIdx.x;
    const int wid  = tid >> 5;
    const int lane = tid & 31;
    const int m0 = blockIdx.x * BM;
    const int n0 = blockIdx.y * BN;
    const int wm = (wid & 1) * 64;   // 2 warps in m
    const int wn = (wid >> 1) * 32;  // 2 warps in n

    const uint32_t sbase = smem_u32(smem);
    const __nv_bfloat16* gA = g_hid + (size_t)m0 * DMODEL;
    const __nv_bfloat16* gB = g_wt  + (size_t)n0 * DMODEL;

    // Per-thread cp.async coords: A 1024 chunks -> 8/thread; B 512 chunks -> 4/thread
    int lcoA[8], lcoB[4];
    const __nv_bfloat16* lsa[8];
    const __nv_bfloat16* lsb[4];
    #pragma unroll
    for (int i = 0; i < 8; i++) {
        int idx = tid + i * 128;
        int r = idx >> 3, c = idx & 7;
        lcoA[i] = r * 128 + ((c ^ (r & 7)) << 4);
        lsa[i]  = gA + (size_t)r * DMODEL + c * 8;
    }
    #pragma unroll
    for (int i = 0; i < 4; i++) {
        int idx = tid + i * 128;
        int r = idx >> 3, c = idx & 7;
        lcoB[i] = r * 128 + ((c ^ (r & 7)) << 4);
        lsb[i]  = gB + (size_t)r * DMODEL + c * 8;
    }

    float acc[4][4][4];
    #pragma unroll
    for (int f = 0; f < 4; f++)
        #pragma unroll
        for (int j = 0; j < 4; j++)
            #pragma unroll
            for (int q = 0; q < 4; q++) acc[f][j][q] = 0.f;

    // ---- prefetch STAGES-1 stages ----
    #pragma unroll
    for (int s = 0; s < STAGES - 1; s++) {
        uint32_t dstA = sbase + s * STAGE_BYTES;
        uint32_t dstB = dstA + A_TILE_BYTES;
        #pragma unroll
        for (int i = 0; i < 8; i++) cp16(dstA + lcoA[i], lsa[i] + s * BK);
        #pragma unroll
        for (int i = 0; i < 4; i++) cp16(dstB + lcoB[i], lsb[i] + s * BK);
        asm volatile("cp.async.commit_group;");
    }

    const int lrow = lane & 15;
    const int lhi  = lane >> 4;

    #pragma unroll 3
    for (int kc = 0; kc < NKC; kc++) {
        asm volatile("cp.async.wait_group %0;" :: "n"(STAGES - 2));
        __syncthreads();

        const int st = kc % STAGES;
        const uint32_t baseA = sbase + st * STAGE_BYTES;
        const uint32_t baseB = baseA + A_TILE_BYTES;

        // issue next-stage loads first (deeper latency hiding)
        const int nk = kc + STAGES - 1;
        if (nk < NKC) {
            const int st2 = nk % STAGES;
            uint32_t dstA = sbase + st2 * STAGE_BYTES;
            uint32_t dstB = dstA + A_TILE_BYTES;
            #pragma unroll
            for (int i = 0; i < 8; i++) cp16(dstA + lcoA[i], lsa[i] + nk * BK);
            #pragma unroll
            for (int i = 0; i < 4; i++) cp16(dstB + lcoB[i], lsb[i] + nk * BK);
        }
        asm volatile("cp.async.commit_group;");

        #pragma unroll
        for (int kk = 0; kk < 4; kk++) {
            const int c = kk * 2 + lhi;  // 16B-chunk col
            uint32_t a[4][4], b[2][4];
            #pragma unroll
            for (int f = 0; f < 4; f++) {
                int r = wm + f * 16 + lrow;
                ldsm4(a[f], baseA + r * 128 + ((c ^ (r & 7)) << 4));
            }
            #pragma unroll
            for (int g = 0; g < 2; g++) {
                int r = wn + g * 16 + lrow;
                ldsm4(b[g], baseB + r * 128 + ((c ^ (r & 7)) << 4));
            }
            #pragma unroll
            for (int f = 0; f < 4; f++)
                #pragma unroll
                for (int g = 0; g < 2; g++) {
                    mma16816(acc[f][2 * g + 0], a[f], b[g][0], b[g][2]);
                    mma16816(acc[f][2 * g + 1], a[f], b[g][1], b[g][3]);
                }
        }
    }

    // ---- epilogue: out = acc + float(bias); scalar 4B stores (VOCAB odd) ----
    float fb0[4], fb1[4];
    #pragma unroll
    for (int j = 0; j < 4; j++) {
        const int col = n0 + wn + j * 8 + ((lane & 3) << 1);
        fb0[j] = g_fb[col];
        fb1[j] = g_fb[col + 1 < VPAD ? col + 1 : col];
    }
    #pragma unroll
    for (int f = 0; f < 4; f++) {
        const int r = m0 + wm + f * 16 + (lane >> 2);
        float* row0 = out + (size_t)r * VOCAB;
        float* row1 = row0 + (size_t)8 * VOCAB;
        #pragma unroll
        for (int j = 0; j < 4; j++) {
            const int col = n0 + wn + j * 8 + ((lane & 3) << 1);
            if (col < VOCAB) {
                row0[col] = acc[f][j][0] + fb0[j];
                row1[col] = acc[f][j][2] + fb0[j];
            }
            if (col + 1 < VOCAB) {
                row0[col + 1] = acc[f][j][1] + fb1[j];
                row1[col + 1] = acc[f][j][3] + fb1[j];
            }
        }
    }
}

// ---------------- launch ----------------
extern "C" void kernel_launch(void* const* d_in, const int* in_sizes, int n_in,
                              void* d_out, int out_size) {
    const int* ids  = (const int*)d_in[0];   // [2,2048] int32
    const int* wte  = (const int*)d_in[1];   // [50257,768] int8 widened to int32
    const int* wpe  = (const int*)d_in[2];   // [2048,768] int8 widened to int32
    const int* w    = (const int*)d_in[3];   // [768,50257] int32
    const int* bias = (const int*)d_in[4];   // [50257] int32
    float* out = (float*)d_out;              // [2,2048,50257] float32

    cudaFuncSetAttribute(gemm_kernel, cudaFuncAttributeMaxDynamicSharedMemorySize, SMEM_BYTES);

    prep_kernel<<<PREP_GRID, 256>>>(ids, wte, wpe, w, bias);
    gemm_kernel<<<dim3(MTOT / BM, VPAD / BN), 128, SMEM_BYTES>>>(out);
}